// round 11
// baseline (speedup 1.0000x reference)
#include <cuda_runtime.h>
#include <cstdint>

// Problem dims
static constexpr int Bn = 32, Tn = 10, Dn = 10, Un = 50, Pn = 50, En = 256;
static constexpr int Rr = 64;
static constexpr int SA  = 260;  // sX/sK row stride; 260%32==4
static constexpr int SSs = 68;   // sS row stride; 68%32==4
static constexpr int SVT = 68;   // sVT row stride (256 e-rows x (64 p + pad))
static constexpr int SWr = 36;   // staged W row stride (256 n-rows x (32 k + pad))
static constexpr int THREADS = 512;

static constexpr int OFF_X  = 0;
static constexpr int OFF_K  = Rr * SA;                 // 16640
static constexpr int OFF_R3 = 2 * Rr * SA;             // 33280 (sVT 17408 | Wbuf 18432)
static constexpr int OFF_S  = OFF_R3 + 2 * 256 * SWr;  // 51712
static constexpr int SMEM_FLOATS = OFF_S + Rr * SSs;   // 56064
static constexpr int SMEM_BYTES  = SMEM_FLOATS * 4;    // 224256

// in-32-block k permutation: sigma(k) = (k%4)*8 + (k%32)/4  (+ block base)
__device__ __forceinline__ int perm32(int c) { return (c & ~31) | (((c & 3) << 3) | ((c & 31) >> 2)); }
__device__ __forceinline__ int inv32lo(int l) { return ((l & 7) << 2) | ((l & 31) >> 3); }

__device__ __forceinline__ float wsum(float v) {
#pragma unroll
    for (int o = 16; o > 0; o >>= 1) v += __shfl_xor_sync(0xffffffffu, v, o);
    return v;
}
__device__ __forceinline__ float wmax(float v) {
#pragma unroll
    for (int o = 16; o > 0; o >>= 1) v = fmaxf(v, __shfl_xor_sync(0xffffffffu, v, o));
    return v;
}

// RNA tf32 rounding (producer-side, for B operands)
__device__ __forceinline__ uint32_t f2tf(float f) {
    uint32_t r;
    asm("cvt.rna.tf32.f32 %0, %1;" : "=r"(r) : "f"(f));
    return r;
}
__device__ __forceinline__ float tfr(float f) { return __uint_as_float(f2tf(f)); }

#define F4E(v, i) ((i) == 0 ? (v).x : (i) == 1 ? (v).y : (i) == 2 ? (v).z : (v).w)
#define BITS(v, i) __float_as_uint(F4E(v, i))

__device__ __forceinline__ void mma_tf32(float c[4],
                                         uint32_t a0, uint32_t a1, uint32_t a2, uint32_t a3,
                                         uint32_t b0, uint32_t b1) {
    asm("mma.sync.aligned.m16n8k8.row.col.f32.tf32.tf32.f32 "
        "{%0,%1,%2,%3}, {%4,%5,%6,%7}, {%8,%9}, {%0,%1,%2,%3};"
        : "+f"(c[0]), "+f"(c[1]), "+f"(c[2]), "+f"(c[3])
        : "r"(a0), "r"(a1), "r"(a2), "r"(a3), "r"(b0), "r"(b1));
}

// stage one W row (32 k in 8 float4 regs) into n-major k-permuted layout,
// RNA-rounded to tf32. Conflict-free per quarter-warp (bank = 4n+off pattern).
__device__ __forceinline__ void stage_w(float* buf, int n, const float4 w[8]) {
    float* dst = buf + n * SWr;
#pragma unroll
    for (int j0 = 0; j0 < 4; ++j0) {
        float4 ge = make_float4(tfr(F4E(w[0], j0)), tfr(F4E(w[1], j0)),
                                tfr(F4E(w[2], j0)), tfr(F4E(w[3], j0)));
        float4 go = make_float4(tfr(F4E(w[4], j0)), tfr(F4E(w[5], j0)),
                                tfr(F4E(w[6], j0)), tfr(F4E(w[7], j0)));
        *reinterpret_cast<float4*>(dst + j0 * 8)     = ge;
        *reinterpret_cast<float4*>(dst + j0 * 8 + 4) = go;
    }
}

// C[64][256] = A[64][256] @ W^T. A in smem (E-permuted, stride SA); W global
// [256n][256k] staged n-major k-permuted, double-buffered 32-k chunks.
// Staging split: group sg==0 (tid<256) stages even chunks, sg==1 odd chunks,
// LDG two chunks ahead. Warp tile m16 x n64.
__device__ __forceinline__ void ffn_mma(
    const float* __restrict__ Wg, const float* __restrict__ sA, float* __restrict__ sWb,
    float acc[8][4], int nrow, int sg, int g, int t, int mb, int nb)
{
    float4 wreg[8];
    const float* wrow = Wg + nrow * En;
    if (sg == 0) {
#pragma unroll
        for (int i = 0; i < 8; ++i)
            wreg[i] = *reinterpret_cast<const float4*>(wrow + i * 4);
    }
    __syncthreads();                 // prior phase done: sA final, sWb region free
    if (sg == 0) stage_w(sWb, nrow, wreg);
    else {
#pragma unroll
        for (int i = 0; i < 8; ++i)
            wreg[i] = *reinterpret_cast<const float4*>(wrow + 32 + i * 4);
    }
    __syncthreads();                 // chunk 0 visible
#pragma unroll
    for (int c = 0; c < 8; ++c) {
        const float* buf = sWb + (c & 1) * (256 * SWr);
        float4 aA[2][2];
        {
            const float* p0 = sA + (mb + g) * SA + c * 32 + 8 * t;
            const float* p1 = p0 + 8 * SA;
            aA[0][0] = *reinterpret_cast<const float4*>(p0);
            aA[0][1] = *reinterpret_cast<const float4*>(p0 + 4);
            aA[1][0] = *reinterpret_cast<const float4*>(p1);
            aA[1][1] = *reinterpret_cast<const float4*>(p1 + 4);
        }
#pragma unroll
        for (int q = 0; q < 8; ++q) {
            const float* pb = buf + (nb + q * 8 + g) * SWr + 8 * t;
            float4 b0 = *reinterpret_cast<const float4*>(pb);
            float4 b1 = *reinterpret_cast<const float4*>(pb + 4);
#pragma unroll
            for (int h = 0; h < 4; ++h) {
                const int sel = h >> 1, e0 = 2 * (h & 1), e1 = e0 + 1;
                const float4& bb = sel ? b1 : b0;
                mma_tf32(acc[q],
                         BITS(aA[0][sel], e0), BITS(aA[1][sel], e0),
                         BITS(aA[0][sel], e1), BITS(aA[1][sel], e1),
                         BITS(bb, e0), BITS(bb, e1));
            }
        }
        if (c < 7 && sg == ((c + 1) & 1))
            stage_w(sWb + ((c + 1) & 1) * (256 * SWr), nrow, wreg);
        if (c < 6 && sg == (c & 1)) {
#pragma unroll
            for (int i = 0; i < 8; ++i)
                wreg[i] = *reinterpret_cast<const float4*>(wrow + (c + 2) * 32 + i * 4);
        }
        __syncthreads();
    }
}

__global__ __launch_bounds__(THREADS, 1)
void fusion_block_kernel(
    const float* __restrict__ Qg_, const float* __restrict__ Kg_,
    const float* __restrict__ Vg_, const float* __restrict__ Mg_,
    const float* __restrict__ W1, const float* __restrict__ b1,
    const float* __restrict__ W2, const float* __restrict__ b2,
    const float* __restrict__ ln1w, const float* __restrict__ ln1b,
    const float* __restrict__ ln2w, const float* __restrict__ ln2b,
    float* __restrict__ Out)
{
    extern __shared__ float sm[];
    float* sX  = sm + OFF_X;    // Q -> x residual (E-permuted, fp32)
    float* sK  = sm + OFF_K;    // K (E-perm, rounded) -> H (E2-perm)
    float* sR3 = sm + OFF_R3;   // sVT [256 e][p-perm] -> W double buffer
    float* sS  = sm + OFF_S;    // scores/probs (p-permuted cols)

    const int tid  = threadIdx.x;
    const int warp = tid >> 5;
    const int lane = tid & 31;
    const int g    = lane >> 2;
    const int t    = lane & 3;
    const int nrow = tid & 255;     // staged W row
    const int sg   = tid >> 8;      // staging group

    const int bid = blockIdx.x;
    const int bt  = bid / Dn;
    const int d   = bid - bt * Dn;
    const int b   = bt / Tn;
    const int bd  = b * Dn + d;

    const float* Qg = Qg_ + (size_t)bt  * (Un * En);
    const float* Kg = Kg_ + (size_t)bd  * (Pn * En);
    const float* Vg = Vg_ + (size_t)bd  * (Pn * En);
    const float* Mg = Mg_ + (size_t)bid * (Un * Pn);
    float*       Og = Out + (size_t)bid * (Un * En);

    const float4 z4 = make_float4(0.f, 0.f, 0.f, 0.f);

    // ---- Load Q,K (E-permuted granule assembly; K RNA-rounded) ----
#pragma unroll
    for (int it = 0; it < 2; ++it) {
        int idx = tid + it * THREADS;   // 64 rows x 16 half-blocks
        int row = idx & 63;
        int hb  = idx >> 6;
        float4 q[4], k[4];
#pragma unroll
        for (int m = 0; m < 4; ++m) {
            if (row < Un) {
                q[m] = *reinterpret_cast<const float4*>(Qg + row * En + hb * 16 + m * 4);
                k[m] = *reinterpret_cast<const float4*>(Kg + row * En + hb * 16 + m * 4);
            } else { q[m] = z4; k[m] = z4; }
        }
        int dst = row * SA + (hb >> 1) * 32 + (hb & 1) * 4;
#pragma unroll
        for (int j0 = 0; j0 < 4; ++j0) {
            *reinterpret_cast<float4*>(sX + dst + j0 * 8) =
                make_float4(F4E(q[0], j0), F4E(q[1], j0), F4E(q[2], j0), F4E(q[3], j0));
            *reinterpret_cast<float4*>(sK + dst + j0 * 8) =
                make_float4(tfr(F4E(k[0], j0)), tfr(F4E(k[1], j0)),
                            tfr(F4E(k[2], j0)), tfr(F4E(k[3], j0)));
        }
    }
    // ---- Load V transposed (RNA-rounded): sVT[e][perm(p)] ----
#pragma unroll
    for (int it = 0; it < 8; ++it) {
        int idx = tid + it * THREADS;   // 64 p x 64 e-quads
        int p   = idx & 63;
        int eq  = idx >> 6;
        float4 v = (p < Un) ? *reinterpret_cast<const float4*>(Vg + p * En + eq * 4) : z4;
        int sp = perm32(p);
#pragma unroll
        for (int j = 0; j < 4; ++j)
            sR3[(eq * 4 + j) * SVT + sp] = tfr(F4E(v, j));
    }
    __syncthreads();

    // ---- S = Q K^T / 16 + mask  (warp tile m16 x n16) ----
    {
        const int mbS = (warp & 3) * 16;
        const int nbS = (warp >> 2) * 16;
        float acc[2][4] = {};
#pragma unroll
        for (int kb = 0; kb < 8; ++kb) {
            float4 aA[2][2], bB[2][2];
            {
                const float* p0 = sX + (mbS + g) * SA + kb * 32 + 8 * t;
                const float* p1 = p0 + 8 * SA;
                aA[0][0] = *reinterpret_cast<const float4*>(p0);
                aA[0][1] = *reinterpret_cast<const float4*>(p0 + 4);
                aA[1][0] = *reinterpret_cast<const float4*>(p1);
                aA[1][1] = *reinterpret_cast<const float4*>(p1 + 4);
                const float* pk0 = sK + (nbS + g) * SA + kb * 32 + 8 * t;
                const float* pk1 = pk0 + 8 * SA;
                bB[0][0] = *reinterpret_cast<const float4*>(pk0);
                bB[0][1] = *reinterpret_cast<const float4*>(pk0 + 4);
                bB[1][0] = *reinterpret_cast<const float4*>(pk1);
                bB[1][1] = *reinterpret_cast<const float4*>(pk1 + 4);
            }
#pragma unroll
            for (int h = 0; h < 4; ++h) {
                const int sel = h >> 1, e0 = 2 * (h & 1), e1 = e0 + 1;
#pragma unroll
                for (int nt = 0; nt < 2; ++nt)
                    mma_tf32(acc[nt],
                             BITS(aA[0][sel], e0), BITS(aA[1][sel], e0),
                             BITS(aA[0][sel], e1), BITS(aA[1][sel], e1),
                             BITS(bB[nt][sel], e0), BITS(bB[nt][sel], e1));
            }
        }
        const float inv_scale = 1.0f / 16.0f;  // sqrt(256)+1e-8 == 16.0f
#pragma unroll
        for (int nt = 0; nt < 2; ++nt)
#pragma unroll
            for (int r = 0; r < 4; ++r) {
                int u = mbS + g + (r >= 2 ? 8 : 0);
                int p = nbS + nt * 8 + 2 * t + (r & 1);
                float s = acc[nt][r] * inv_scale;
                if (u < Un && p < Pn) s += Mg[u * Pn + p];
                sS[u * SSs + perm32(p)] = s;
            }
    }
    __syncthreads();

    // ---- softmax over p (cols p-permuted); probs RNA-rounded ----
    {
        const bool val1 = (inv32lo(lane) < Pn - 32);
#pragma unroll
        for (int r = 0; r < 4; ++r) {
            int row = warp * 4 + r;
            float v0 = sS[row * SSs + lane];
            float v1 = val1 ? sS[row * SSs + lane + 32] : -1e30f;
            float m  = wmax(fmaxf(v0, v1));
            float e0 = __expf(v0 - m);
            float e1 = val1 ? __expf(v1 - m) : 0.f;
            float inv = 1.f / wsum(e0 + e1);
            sS[row * SSs + lane]      = tfr(e0 * inv);
            sS[row * SSs + lane + 32] = tfr(e1 * inv);
        }
    }
    __syncthreads();

    const int mb = (warp & 3) * 16;
    const int nb = (warp >> 2) * 64;

    // ---- v_att = S @ V (warp tile m16 x n64); x = Q + v_att ----
    {
        float acc[8][4] = {};
#pragma unroll
        for (int kb = 0; kb < 2; ++kb) {
            float4 aA[2][2];
            {
                const float* p0 = sS + (mb + g) * SSs + kb * 32 + 8 * t;
                const float* p1 = p0 + 8 * SSs;
                aA[0][0] = *reinterpret_cast<const float4*>(p0);
                aA[0][1] = *reinterpret_cast<const float4*>(p0 + 4);
                aA[1][0] = *reinterpret_cast<const float4*>(p1);
                aA[1][1] = *reinterpret_cast<const float4*>(p1 + 4);
            }
#pragma unroll
            for (int q = 0; q < 8; ++q) {
                const float* pb = sR3 + (nb + q * 8 + g) * SVT + kb * 32 + 8 * t;
                float4 b0 = *reinterpret_cast<const float4*>(pb);
                float4 b1 = *reinterpret_cast<const float4*>(pb + 4);
#pragma unroll
                for (int h = 0; h < 4; ++h) {
                    const int sel = h >> 1, e0 = 2 * (h & 1), e1 = e0 + 1;
                    const float4& bb = sel ? b1 : b0;
                    mma_tf32(acc[q],
                             BITS(aA[0][sel], e0), BITS(aA[1][sel], e0),
                             BITS(aA[0][sel], e1), BITS(aA[1][sel], e1),
                             BITS(bb, e0), BITS(bb, e1));
                }
            }
        }
#pragma unroll
        for (int q = 0; q < 8; ++q) {
            int row0 = mb + g;
            int col  = nb + q * 8 + 2 * t;
            int sc0 = perm32(col), sc1 = perm32(col + 1);
            sX[row0 * SA + sc0]       += acc[q][0];
            sX[row0 * SA + sc1]       += acc[q][1];
            sX[(row0 + 8) * SA + sc0] += acc[q][2];
            sX[(row0 + 8) * SA + sc1] += acc[q][3];
        }
    }
    __syncthreads();

    // ---- LN1 (4 rows per warp; weights via inverse perm) ----
    {
#pragma unroll
        for (int r = 0; r < 4; ++r) {
            int row = warp * 4 + r;
            float xv[8];
            float s = 0.f;
#pragma unroll
            for (int kk = 0; kk < 8; ++kk) { xv[kk] = sX[row * SA + lane + kk * 32]; s += xv[kk]; }
            float mu = wsum(s) * (1.f / En);
            float vs = 0.f;
#pragma unroll
            for (int kk = 0; kk < 8; ++kk) { float t2 = xv[kk] - mu; vs += t2 * t2; }
            float rstd = rsqrtf(wsum(vs) * (1.f / En) + 1e-5f);
            int eb = inv32lo(lane);
#pragma unroll
            for (int kk = 0; kk < 8; ++kk) {
                int e = kk * 32 + eb;
                sX[row * SA + lane + kk * 32] = (xv[kk] - mu) * rstd * ln1w[e] + ln1b[e];
            }
        }
    }
    // (first barrier inside ffn_mma orders LN1 writes, retires sVT region)

    // ---- FFN1: H = relu(x @ W1^T + b1) -> sK (E2-permuted) ----
    {
        float acc[8][4] = {};
        ffn_mma(W1, sX, sR3, acc, nrow, sg, g, t, mb, nb);
#pragma unroll
        for (int q = 0; q < 8; ++q) {
            int row0 = mb + g;
            int col  = nb + q * 8 + 2 * t;
            float bb0 = __ldg(b1 + col), bb1 = __ldg(b1 + col + 1);
            int sc0 = perm32(col), sc1 = perm32(col + 1);
            sK[row0 * SA + sc0]       = fmaxf(acc[q][0] + bb0, 0.f);
            sK[row0 * SA + sc1]       = fmaxf(acc[q][1] + bb1, 0.f);
            sK[(row0 + 8) * SA + sc0] = fmaxf(acc[q][2] + bb0, 0.f);
            sK[(row0 + 8) * SA + sc1] = fmaxf(acc[q][3] + bb1, 0.f);
        }
    }

    // ---- FFN2: y = H @ W2^T + b2 + x (into sX, fp32) ----
    {
        float acc[8][4] = {};
        ffn_mma(W2, sK, sR3, acc, nrow, sg, g, t, mb, nb);
#pragma unroll
        for (int q = 0; q < 8; ++q) {
            int row0 = mb + g;
            int col  = nb + q * 8 + 2 * t;
            float bb0 = __ldg(b2 + col), bb1 = __ldg(b2 + col + 1);
            int sc0 = perm32(col), sc1 = perm32(col + 1);
            sX[row0 * SA + sc0]       += acc[q][0] + bb0;
            sX[row0 * SA + sc1]       += acc[q][1] + bb1;
            sX[(row0 + 8) * SA + sc0] += acc[q][2] + bb0;
            sX[(row0 + 8) * SA + sc1] += acc[q][3] + bb1;
        }
    }
    __syncthreads();

    // ---- LN2 + store (de-permute via inverse; line-coalesced) ----
    {
#pragma unroll
        for (int r = 0; r < 4; ++r) {
            int row = warp * 4 + r;
            if (row >= Un) break;    // uniform per warp
            float xv[8];
            float s = 0.f;
#pragma unroll
            for (int kk = 0; kk < 8; ++kk) { xv[kk] = sX[row * SA + lane + kk * 32]; s += xv[kk]; }
            float mu = wsum(s) * (1.f / En);
            float vs = 0.f;
#pragma unroll
            for (int kk = 0; kk < 8; ++kk) { float t2 = xv[kk] - mu; vs += t2 * t2; }
            float rstd = rsqrtf(wsum(vs) * (1.f / En) + 1e-5f);
            int eb = inv32lo(lane);
#pragma unroll
            for (int kk = 0; kk < 8; ++kk) {
                int e = kk * 32 + eb;
                Og[row * En + e] = (xv[kk] - mu) * rstd * ln2w[e] + ln2b[e];
            }
        }
    }
}

extern "C" void kernel_launch(void* const* d_in, const int* in_sizes, int n_in,
                              void* d_out, int out_size) {
    (void)in_sizes; (void)n_in; (void)out_size;
    cudaFuncSetAttribute(fusion_block_kernel,
                         cudaFuncAttributeMaxDynamicSharedMemorySize, SMEM_BYTES);
    fusion_block_kernel<<<Bn * Tn * Dn, THREADS, SMEM_BYTES>>>(
        (const float*)d_in[0],  // Q
        (const float*)d_in[1],  // K
        (const float*)d_in[2],  // V
        (const float*)d_in[3],  // attention_mask
        (const float*)d_in[4],  // W1
        (const float*)d_in[5],  // b1
        (const float*)d_in[6],  // W2
        (const float*)d_in[7],  // b2
        (const float*)d_in[8],  // ln1_w
        (const float*)d_in[9],  // ln1_b
        (const float*)d_in[10], // ln2_w
        (const float*)d_in[11], // ln2_b
        (float*)d_out);
}

// round 12
// speedup vs baseline: 1.0631x; 1.0631x over previous
#include <cuda_runtime.h>
#include <cstdint>

// Problem dims
static constexpr int Bn = 32, Tn = 10, Dn = 10, Un = 50, Pn = 50, En = 256;
static constexpr int Rr = 64;
static constexpr int SA  = 260;  // sX/sK row stride; 260%32==4
static constexpr int SSs = 68;   // sS row stride; 68%32==4
static constexpr int SVT = 68;   // sVT row stride (256 e-rows x (64 p + pad))
static constexpr int SWr = 36;   // staged W row stride (256 n-rows x (32 k + pad))
static constexpr int THREADS = 256;

static constexpr int OFF_X  = 0;
static constexpr int OFF_K  = Rr * SA;                 // 16640
static constexpr int OFF_R3 = 2 * Rr * SA;             // 33280 (sVT 17408 | Wbuf 18432)
static constexpr int OFF_S  = OFF_R3 + 2 * 256 * SWr;  // 51712
static constexpr int SMEM_FLOATS = OFF_S + Rr * SSs;   // 56064
static constexpr int SMEM_BYTES  = SMEM_FLOATS * 4;    // 224256

// Pre-permuted, tf32-rounded weights: [w][n][perm(k)]
__device__ float Wp[2][256][256];

// in-32-block k permutation: sigma(k) = (k%4)*8 + (k%32)/4  (+ block base)
__device__ __forceinline__ int perm32(int c) { return (c & ~31) | (((c & 3) << 3) | ((c & 31) >> 2)); }
__device__ __forceinline__ int inv32lo(int l) { return ((l & 7) << 2) | ((l & 31) >> 3); }

__device__ __forceinline__ float wsum(float v) {
#pragma unroll
    for (int o = 16; o > 0; o >>= 1) v += __shfl_xor_sync(0xffffffffu, v, o);
    return v;
}
__device__ __forceinline__ float wmax(float v) {
#pragma unroll
    for (int o = 16; o > 0; o >>= 1) v = fmaxf(v, __shfl_xor_sync(0xffffffffu, v, o));
    return v;
}

// RNA tf32 rounding (producer-side, B operands)
__device__ __forceinline__ uint32_t f2tf(float f) {
    uint32_t r;
    asm("cvt.rna.tf32.f32 %0, %1;" : "=r"(r) : "f"(f));
    return r;
}
__device__ __forceinline__ float tfr(float f) { return __uint_as_float(f2tf(f)); }

#define F4E(v, i) ((i) == 0 ? (v).x : (i) == 1 ? (v).y : (i) == 2 ? (v).z : (v).w)
#define BITS(v, i) __float_as_uint(F4E(v, i))

__device__ __forceinline__ void mma_tf32(float c[4],
                                         uint32_t a0, uint32_t a1, uint32_t a2, uint32_t a3,
                                         uint32_t b0, uint32_t b1) {
    asm("mma.sync.aligned.m16n8k8.row.col.f32.tf32.tf32.f32 "
        "{%0,%1,%2,%3}, {%4,%5,%6,%7}, {%8,%9}, {%0,%1,%2,%3};"
        : "+f"(c[0]), "+f"(c[1]), "+f"(c[2]), "+f"(c[3])
        : "r"(a0), "r"(a1), "r"(a2), "r"(a3), "r"(b0), "r"(b1));
}

// ---- cp.async helpers ----
__device__ __forceinline__ void cpa16(uint32_t dst_smem, const void* src) {
    asm volatile("cp.async.cg.shared.global [%0], [%1], 16;" :: "r"(dst_smem), "l"(src));
}
__device__ __forceinline__ void cp_commit() { asm volatile("cp.async.commit_group;" ::: "memory"); }
__device__ __forceinline__ void cp_wait0()  { asm volatile("cp.async.wait_group 0;" ::: "memory"); }

// stage one 32-k chunk of pre-permuted W row n=tid via 8 x cp.async.16
__device__ __forceinline__ void stage_async(int w, int c, uint32_t sWb_u32, int tid) {
    const float* src = &Wp[w][tid][c * 32];       // 128B line-contiguous per thread
    uint32_t dst = sWb_u32 + (uint32_t)(((c & 1) * (256 * SWr) + tid * SWr) * 4);
#pragma unroll
    for (int j = 0; j < 8; ++j)
        cpa16(dst + j * 16, src + j * 4);
    cp_commit();
}

// C[64][256] = A[64][256] @ W^T. A in smem (E-permuted, stride SA); W from the
// pre-permuted copy Wp[w], cp.async-staged n-major k-permuted, double-buffered
// 32-k chunks, one barrier per chunk. Warp tile m32 x n64 (R10-proven).
__device__ __forceinline__ void ffn_mma(
    int w, const float* sA, const float* sWb, uint32_t sWb_u32,
    float acc[2][8][4], int tid, int g, int t, int mb, int nb)
{
    __syncthreads();                 // prior phase done: sA final, sWb region free
    stage_async(w, 0, sWb_u32, tid);
#pragma unroll
    for (int c = 0; c < 8; ++c) {
        cp_wait0();                  // this thread's pending copies (chunk c) done
        __syncthreads();             // all threads' chunk-c copies visible; compute(c-1) finished
        if (c < 7)
            stage_async(w, c + 1, sWb_u32, tid);   // into buffer freed by compute(c-1)
        const float* buf = sWb + (c & 1) * (256 * SWr);
        float4 aA[4][2];
#pragma unroll
        for (int r4 = 0; r4 < 4; ++r4) {
            int row = mb + (r4 & 1) * 8 + (r4 >> 1) * 16 + g;
            const float* p = sA + row * SA + c * 32 + 8 * t;
            aA[r4][0] = *reinterpret_cast<const float4*>(p);
            aA[r4][1] = *reinterpret_cast<const float4*>(p + 4);
        }
#pragma unroll
        for (int ntg = 0; ntg < 2; ++ntg) {
            float4 bB[4][2];
#pragma unroll
            for (int q = 0; q < 4; ++q) {
                int n = nb + (ntg * 4 + q) * 8 + g;
                const float* p = buf + n * SWr + 8 * t;
                bB[q][0] = *reinterpret_cast<const float4*>(p);
                bB[q][1] = *reinterpret_cast<const float4*>(p + 4);
            }
#pragma unroll
            for (int h = 0; h < 4; ++h) {
                const int sel = h >> 1, e0 = 2 * (h & 1), e1 = e0 + 1;
#pragma unroll
                for (int q = 0; q < 4; ++q) {
                    uint32_t b0 = BITS(bB[q][sel], e0), b1 = BITS(bB[q][sel], e1);
#pragma unroll
                    for (int mf = 0; mf < 2; ++mf) {
                        mma_tf32(acc[mf][ntg * 4 + q],
                                 BITS(aA[2 * mf][sel], e0), BITS(aA[2 * mf + 1][sel], e0),
                                 BITS(aA[2 * mf][sel], e1), BITS(aA[2 * mf + 1][sel], e1),
                                 b0, b1);
                    }
                }
            }
        }
    }
}

// ---- pre-pass: permute + tf32-round W1/W2 into Wp ----
__global__ void permute_w_kernel(const float* __restrict__ W1, const float* __restrict__ W2) {
    int r = blockIdx.x;              // 0..511
    int k = threadIdx.x;             // 0..255
    int n = r & 255;
    const float* W = (r < 256) ? W1 : W2;
    Wp[r >> 8][n][perm32(k)] = tfr(W[n * 256 + k]);
}

__global__ __launch_bounds__(THREADS, 1)
void fusion_block_kernel(
    const float* __restrict__ Qg_, const float* __restrict__ Kg_,
    const float* __restrict__ Vg_, const float* __restrict__ Mg_,
    const float* __restrict__ b1, const float* __restrict__ b2,
    const float* __restrict__ ln1w, const float* __restrict__ ln1b,
    const float* __restrict__ ln2w, const float* __restrict__ ln2b,
    float* __restrict__ Out)
{
    extern __shared__ float sm[];
    float* sX  = sm + OFF_X;    // Q -> x residual (E-permuted, fp32)
    float* sK  = sm + OFF_K;    // K (E-perm, rounded) -> H (E2-perm)
    float* sR3 = sm + OFF_R3;   // sVT [256 e][p-perm] -> W double buffer
    float* sS  = sm + OFF_S;    // scores/probs (p-permuted cols)
    const uint32_t sR3_u32 = (uint32_t)__cvta_generic_to_shared(sR3);

    const int tid  = threadIdx.x;
    const int warp = tid >> 5;
    const int lane = tid & 31;
    const int g    = lane >> 2;
    const int t    = lane & 3;

    const int bid = blockIdx.x;
    const int bt  = bid / Dn;
    const int d   = bid - bt * Dn;
    const int b   = bt / Tn;
    const int bd  = b * Dn + d;

    const float* Qg = Qg_ + (size_t)bt  * (Un * En);
    const float* Kg = Kg_ + (size_t)bd  * (Pn * En);
    const float* Vg = Vg_ + (size_t)bd  * (Pn * En);
    const float* Mg = Mg_ + (size_t)bid * (Un * Pn);
    float*       Og = Out + (size_t)bid * (Un * En);

    const float4 z4 = make_float4(0.f, 0.f, 0.f, 0.f);

    // ---- Load Q,K (E-permuted granule assembly; K RNA-rounded) ----
#pragma unroll
    for (int it = 0; it < 4; ++it) {
        int idx = tid + it * THREADS;   // 64 rows x 16 half-blocks
        int row = idx & 63;
        int hb  = idx >> 6;
        float4 q[4], k[4];
#pragma unroll
        for (int m = 0; m < 4; ++m) {
            if (row < Un) {
                q[m] = *reinterpret_cast<const float4*>(Qg + row * En + hb * 16 + m * 4);
                k[m] = *reinterpret_cast<const float4*>(Kg + row * En + hb * 16 + m * 4);
            } else { q[m] = z4; k[m] = z4; }
        }
        int dst = row * SA + (hb >> 1) * 32 + (hb & 1) * 4;
#pragma unroll
        for (int j0 = 0; j0 < 4; ++j0) {
            *reinterpret_cast<float4*>(sX + dst + j0 * 8) =
                make_float4(F4E(q[0], j0), F4E(q[1], j0), F4E(q[2], j0), F4E(q[3], j0));
            *reinterpret_cast<float4*>(sK + dst + j0 * 8) =
                make_float4(tfr(F4E(k[0], j0)), tfr(F4E(k[1], j0)),
                            tfr(F4E(k[2], j0)), tfr(F4E(k[3], j0)));
        }
    }
    // ---- Load V transposed (RNA-rounded): sVT[e][perm(p)] ----
#pragma unroll
    for (int it = 0; it < 16; ++it) {
        int idx = tid + it * THREADS;   // 64 p x 64 e-quads
        int p   = idx & 63;
        int eq  = idx >> 6;
        float4 v = (p < Un) ? *reinterpret_cast<const float4*>(Vg + p * En + eq * 4) : z4;
        int sp = perm32(p);
#pragma unroll
        for (int j = 0; j < 4; ++j)
            sR3[(eq * 4 + j) * SVT + sp] = tfr(F4E(v, j));
    }
    __syncthreads();

    // ---- S = Q K^T / 16 + mask  (warp tile m32 x n16) ----
    {
        const int mbS = (warp & 1) * 32;
        const int nbS = (warp >> 1) * 16;
        float acc[2][2][4] = {};
#pragma unroll
        for (int kb = 0; kb < 8; ++kb) {
            float4 aA[4][2];
#pragma unroll
            for (int r4 = 0; r4 < 4; ++r4) {
                int row = mbS + (r4 & 1) * 8 + (r4 >> 1) * 16 + g;
                const float* p = sX + row * SA + kb * 32 + 8 * t;
                aA[r4][0] = *reinterpret_cast<const float4*>(p);
                aA[r4][1] = *reinterpret_cast<const float4*>(p + 4);
            }
            float4 bB[2][2];
#pragma unroll
            for (int nt = 0; nt < 2; ++nt) {
                const float* p = sK + (nbS + nt * 8 + g) * SA + kb * 32 + 8 * t;
                bB[nt][0] = *reinterpret_cast<const float4*>(p);
                bB[nt][1] = *reinterpret_cast<const float4*>(p + 4);
            }
#pragma unroll
            for (int h = 0; h < 4; ++h) {
                const int sel = h >> 1, e0 = 2 * (h & 1), e1 = e0 + 1;
#pragma unroll
                for (int nt = 0; nt < 2; ++nt) {
                    uint32_t b0 = BITS(bB[nt][sel], e0), b1 = BITS(bB[nt][sel], e1);
#pragma unroll
                    for (int mf = 0; mf < 2; ++mf)
                        mma_tf32(acc[mf][nt],
                                 BITS(aA[2 * mf][sel], e0), BITS(aA[2 * mf + 1][sel], e0),
                                 BITS(aA[2 * mf][sel], e1), BITS(aA[2 * mf + 1][sel], e1),
                                 b0, b1);
                }
            }
        }
        const float inv_scale = 1.0f / 16.0f;  // sqrt(256)+1e-8 == 16.0f
#pragma unroll
        for (int mf = 0; mf < 2; ++mf)
#pragma unroll
            for (int nt = 0; nt < 2; ++nt)
#pragma unroll
                for (int r = 0; r < 4; ++r) {
                    int u = mbS + mf * 16 + g + (r >= 2 ? 8 : 0);
                    int p = nbS + nt * 8 + 2 * t + (r & 1);
                    float s = acc[mf][nt][r] * inv_scale;
                    if (u < Un && p < Pn) s += Mg[u * Pn + p];
                    sS[u * SSs + perm32(p)] = s;
                }
    }
    __syncthreads();

    // ---- softmax over p (cols p-permuted); probs RNA-rounded ----
    {
        const bool val1 = (inv32lo(lane) < Pn - 32);
#pragma unroll
        for (int r = 0; r < 8; ++r) {
            int row = warp * 8 + r;
            float v0 = sS[row * SSs + lane];
            float v1 = val1 ? sS[row * SSs + lane + 32] : -1e30f;
            float m  = wmax(fmaxf(v0, v1));
            float e0 = __expf(v0 - m);
            float e1 = val1 ? __expf(v1 - m) : 0.f;
            float inv = 1.f / wsum(e0 + e1);
            sS[row * SSs + lane]      = tfr(e0 * inv);
            sS[row * SSs + lane + 32] = tfr(e1 * inv);
        }
    }
    __syncthreads();

    const int mb = (warp & 1) * 32;
    const int nb = (warp >> 1) * 64;

    // ---- v_att = S @ V (warp tile m32 x n64); x = Q + v_att ----
    {
        float acc[2][8][4] = {};
#pragma unroll
        for (int kb = 0; kb < 2; ++kb) {
            float4 aA[4][2];
#pragma unroll
            for (int r4 = 0; r4 < 4; ++r4) {
                int row = mb + (r4 & 1) * 8 + (r4 >> 1) * 16 + g;
                const float* p = sS + row * SSs + kb * 32 + 8 * t;
                aA[r4][0] = *reinterpret_cast<const float4*>(p);
                aA[r4][1] = *reinterpret_cast<const float4*>(p + 4);
            }
#pragma unroll
            for (int ntg = 0; ntg < 2; ++ntg) {
                float4 bB[4][2];
#pragma unroll
                for (int q = 0; q < 4; ++q) {
                    const float* p = sR3 + (nb + (ntg * 4 + q) * 8 + g) * SVT + kb * 32 + 8 * t;
                    bB[q][0] = *reinterpret_cast<const float4*>(p);
                    bB[q][1] = *reinterpret_cast<const float4*>(p + 4);
                }
#pragma unroll
                for (int h = 0; h < 4; ++h) {
                    const int sel = h >> 1, e0 = 2 * (h & 1), e1 = e0 + 1;
#pragma unroll
                    for (int q = 0; q < 4; ++q) {
                        uint32_t b0 = BITS(bB[q][sel], e0), b1 = BITS(bB[q][sel], e1);
#pragma unroll
                        for (int mf = 0; mf < 2; ++mf)
                            mma_tf32(acc[mf][ntg * 4 + q],
                                     BITS(aA[2 * mf][sel], e0), BITS(aA[2 * mf + 1][sel], e0),
                                     BITS(aA[2 * mf][sel], e1), BITS(aA[2 * mf + 1][sel], e1),
                                     b0, b1);
                    }
                }
            }
        }
#pragma unroll
        for (int mf = 0; mf < 2; ++mf)
#pragma unroll
            for (int nt = 0; nt < 8; ++nt) {
                int row0 = mb + mf * 16 + g;
                int col  = nb + nt * 8 + 2 * t;
                int sc0 = perm32(col), sc1 = perm32(col + 1);
                sX[row0 * SA + sc0]       += acc[mf][nt][0];
                sX[row0 * SA + sc1]       += acc[mf][nt][1];
                sX[(row0 + 8) * SA + sc0] += acc[mf][nt][2];
                sX[(row0 + 8) * SA + sc1] += acc[mf][nt][3];
            }
    }
    __syncthreads();

    // ---- LN1 (8 rows per warp; weights via inverse perm) ----
    {
#pragma unroll
        for (int r = 0; r < 8; ++r) {
            int row = warp * 8 + r;
            float xv[8];
            float s = 0.f;
#pragma unroll
            for (int kk = 0; kk < 8; ++kk) { xv[kk] = sX[row * SA + lane + kk * 32]; s += xv[kk]; }
            float mu = wsum(s) * (1.f / En);
            float vs = 0.f;
#pragma unroll
            for (int kk = 0; kk < 8; ++kk) { float t2 = xv[kk] - mu; vs += t2 * t2; }
            float rstd = rsqrtf(wsum(vs) * (1.f / En) + 1e-5f);
            int eb = inv32lo(lane);
#pragma unroll
            for (int kk = 0; kk < 8; ++kk) {
                int e = kk * 32 + eb;
                sX[row * SA + lane + kk * 32] = (xv[kk] - mu) * rstd * ln1w[e] + ln1b[e];
            }
        }
    }
    // (first barrier inside ffn_mma orders LN1 writes, retires sVT region)

    // ---- FFN1: H = relu(x @ W1^T + b1) -> sK (E2-permuted) ----
    {
        float acc[2][8][4] = {};
        ffn_mma(0, sX, sR3, sR3_u32, acc, tid, g, t, mb, nb);
#pragma unroll
        for (int mf = 0; mf < 2; ++mf)
#pragma unroll
            for (int nt = 0; nt < 8; ++nt) {
                int row0 = mb + mf * 16 + g;
                int col  = nb + nt * 8 + 2 * t;
                float bb0 = __ldg(b1 + col), bb1 = __ldg(b1 + col + 1);
                int sc0 = perm32(col), sc1 = perm32(col + 1);
                sK[row0 * SA + sc0]       = fmaxf(acc[mf][nt][0] + bb0, 0.f);
                sK[row0 * SA + sc1]       = fmaxf(acc[mf][nt][1] + bb1, 0.f);
                sK[(row0 + 8) * SA + sc0] = fmaxf(acc[mf][nt][2] + bb0, 0.f);
                sK[(row0 + 8) * SA + sc1] = fmaxf(acc[mf][nt][3] + bb1, 0.f);
            }
    }

    // ---- FFN2: y = H @ W2^T + b2 + x (into sX, fp32) ----
    {
        float acc[2][8][4] = {};
        ffn_mma(1, sK, sR3, sR3_u32, acc, tid, g, t, mb, nb);
#pragma unroll
        for (int mf = 0; mf < 2; ++mf)
#pragma unroll
            for (int nt = 0; nt < 8; ++nt) {
                int row0 = mb + mf * 16 + g;
                int col  = nb + nt * 8 + 2 * t;
                float bb0 = __ldg(b2 + col), bb1 = __ldg(b2 + col + 1);
                int sc0 = perm32(col), sc1 = perm32(col + 1);
                sX[row0 * SA + sc0]       += acc[mf][nt][0] + bb0;
                sX[row0 * SA + sc1]       += acc[mf][nt][1] + bb1;
                sX[(row0 + 8) * SA + sc0] += acc[mf][nt][2] + bb0;
                sX[(row0 + 8) * SA + sc1] += acc[mf][nt][3] + bb1;
            }
    }
    __syncthreads();

    // ---- LN2 + store (de-permute via inverse; line-coalesced) ----
    {
#pragma unroll
        for (int r = 0; r < 8; ++r) {
            int row = warp * 8 + r;
            if (row >= Un) break;    // uniform per warp
            float xv[8];
            float s = 0.f;
#pragma unroll
            for (int kk = 0; kk < 8; ++kk) { xv[kk] = sX[row * SA + lane + kk * 32]; s += xv[kk]; }
            float mu = wsum(s) * (1.f / En);
            float vs = 0.f;
#pragma unroll
            for (int kk = 0; kk < 8; ++kk) { float t2 = xv[kk] - mu; vs += t2 * t2; }
            float rstd = rsqrtf(wsum(vs) * (1.f / En) + 1e-5f);
            int eb = inv32lo(lane);
#pragma unroll
            for (int kk = 0; kk < 8; ++kk) {
                int e = kk * 32 + eb;
                Og[row * En + e] = (xv[kk] - mu) * rstd * ln2w[e] + ln2b[e];
            }
        }
    }
}

extern "C" void kernel_launch(void* const* d_in, const int* in_sizes, int n_in,
                              void* d_out, int out_size) {
    (void)in_sizes; (void)n_in; (void)out_size;
    permute_w_kernel<<<512, 256>>>((const float*)d_in[4], (const float*)d_in[6]);
    cudaFuncSetAttribute(fusion_block_kernel,
                         cudaFuncAttributeMaxDynamicSharedMemorySize, SMEM_BYTES);
    fusion_block_kernel<<<Bn * Tn * Dn, THREADS, SMEM_BYTES>>>(
        (const float*)d_in[0],  // Q
        (const float*)d_in[1],  // K
        (const float*)d_in[2],  // V
        (const float*)d_in[3],  // attention_mask
        (const float*)d_in[5],  // b1
        (const float*)d_in[7],  // b2
        (const float*)d_in[8],  // ln1_w
        (const float*)d_in[9],  // ln1_b
        (const float*)d_in[10], // ln2_w
        (const float*)d_in[11], // ln2_b
        (float*)d_out);
}

// round 13
// speedup vs baseline: 1.3403x; 1.2608x over previous
#include <cuda_runtime.h>
#include <cstdint>

// Problem dims
static constexpr int Bn = 32, Tn = 10, Dn = 10, Un = 50, Pn = 50, En = 256;
static constexpr int Rr = 64;
static constexpr int SA  = 260;  // sX/sK row stride; 260%32==4
static constexpr int SSs = 68;   // sS row stride; 68%32==4
static constexpr int SVT = 68;   // sVT row stride (256 e-rows x (64 p + pad))
static constexpr int SWr = 36;   // staged W row stride (256 n-rows x (32 k + pad))
static constexpr int THREADS = 512;

static constexpr int OFF_X  = 0;
static constexpr int OFF_K  = Rr * SA;                 // 16640
static constexpr int OFF_R3 = 2 * Rr * SA;             // 33280 (sVT 17408 | Wbuf 18432)
static constexpr int OFF_S  = OFF_R3 + 2 * 256 * SWr;  // 51712
static constexpr int SMEM_FLOATS = OFF_S + Rr * SSs;   // 56064
static constexpr int SMEM_BYTES  = SMEM_FLOATS * 4;    // 224256

// Pre-permuted, tf32-rounded weights: [w][n][perm(k)]
__device__ float Wp[2][256][256];

// in-32-block k permutation: sigma(k) = (k%4)*8 + (k%32)/4  (+ block base)
__device__ __forceinline__ int perm32(int c) { return (c & ~31) | (((c & 3) << 3) | ((c & 31) >> 2)); }
__device__ __forceinline__ int inv32lo(int l) { return ((l & 7) << 2) | ((l & 31) >> 3); }

__device__ __forceinline__ float wsum(float v) {
#pragma unroll
    for (int o = 16; o > 0; o >>= 1) v += __shfl_xor_sync(0xffffffffu, v, o);
    return v;
}
__device__ __forceinline__ float wmax(float v) {
#pragma unroll
    for (int o = 16; o > 0; o >>= 1) v = fmaxf(v, __shfl_xor_sync(0xffffffffu, v, o));
    return v;
}

// RNA tf32 rounding (producer-side, B operands)
__device__ __forceinline__ uint32_t f2tf(float f) {
    uint32_t r;
    asm("cvt.rna.tf32.f32 %0, %1;" : "=r"(r) : "f"(f));
    return r;
}
__device__ __forceinline__ float tfr(float f) { return __uint_as_float(f2tf(f)); }

#define F4E(v, i) ((i) == 0 ? (v).x : (i) == 1 ? (v).y : (i) == 2 ? (v).z : (v).w)
#define BITS(v, i) __float_as_uint(F4E(v, i))

__device__ __forceinline__ void mma_tf32(float c[4],
                                         uint32_t a0, uint32_t a1, uint32_t a2, uint32_t a3,
                                         uint32_t b0, uint32_t b1) {
    asm("mma.sync.aligned.m16n8k8.row.col.f32.tf32.tf32.f32 "
        "{%0,%1,%2,%3}, {%4,%5,%6,%7}, {%8,%9}, {%0,%1,%2,%3};"
        : "+f"(c[0]), "+f"(c[1]), "+f"(c[2]), "+f"(c[3])
        : "r"(a0), "r"(a1), "r"(a2), "r"(a3), "r"(b0), "r"(b1));
}

// ---- cp.async helpers ----
__device__ __forceinline__ void cpa16(uint32_t dst_smem, const void* src) {
    asm volatile("cp.async.cg.shared.global [%0], [%1], 16;" :: "r"(dst_smem), "l"(src));
}
__device__ __forceinline__ void cp_commit() { asm volatile("cp.async.commit_group;" ::: "memory"); }
__device__ __forceinline__ void cp_wait0()  { asm volatile("cp.async.wait_group 0;" ::: "memory"); }

// stage one 32-k chunk: 512 threads, thread stages 16 k of row n = tid>>1
// (dst banks: n*36 + half*16 -> all 32 banks distinct per 8-thread phase)
__device__ __forceinline__ void stage_async(int w, int c, uint32_t sWb_u32, int tid) {
    const int n = tid >> 1, half = tid & 1;
    const float* src = &Wp[w][n][c * 32 + half * 16];
    uint32_t dst = sWb_u32 + (uint32_t)(((c & 1) * (256 * SWr) + n * SWr + half * 16) * 4);
#pragma unroll
    for (int j = 0; j < 4; ++j)
        cpa16(dst + j * 16, src + j * 4);
    cp_commit();
}

// C[64][256] = A[64][256] @ W^T. A in smem (E-permuted, stride SA); W from
// pre-permuted Wp[w], cp.async-staged, double-buffered 32-k chunks.
// Warp tile m32 x n32 (16 warps: mb=(warp&1)*32, nb=(warp>>1)*32).
__device__ __forceinline__ void ffn_mma(
    int w, const float* sA, const float* sWb, uint32_t sWb_u32,
    float acc[2][4][4], int tid, int g, int t, int mb, int nb)
{
    __syncthreads();                 // prior phase done: sA final, sWb region free
    stage_async(w, 0, sWb_u32, tid);
#pragma unroll
    for (int c = 0; c < 8; ++c) {
        cp_wait0();                  // chunk c copies (committed last iteration) done
        __syncthreads();             // visible block-wide; compute(c-1) finished
        if (c < 7)
            stage_async(w, c + 1, sWb_u32, tid);   // into buffer freed by compute(c-1)
        const float* buf = sWb + (c & 1) * (256 * SWr);
        float4 aA[4][2];
#pragma unroll
        for (int r4 = 0; r4 < 4; ++r4) {
            int row = mb + (r4 & 1) * 8 + (r4 >> 1) * 16 + g;
            const float* p = sA + row * SA + c * 32 + 8 * t;
            aA[r4][0] = *reinterpret_cast<const float4*>(p);
            aA[r4][1] = *reinterpret_cast<const float4*>(p + 4);
        }
        float4 bB[4][2];
#pragma unroll
        for (int q = 0; q < 4; ++q) {
            const float* p = buf + (nb + q * 8 + g) * SWr + 8 * t;
            bB[q][0] = *reinterpret_cast<const float4*>(p);
            bB[q][1] = *reinterpret_cast<const float4*>(p + 4);
        }
#pragma unroll
        for (int h = 0; h < 4; ++h) {
            const int sel = h >> 1, e0 = 2 * (h & 1), e1 = e0 + 1;
#pragma unroll
            for (int q = 0; q < 4; ++q) {
                uint32_t b0 = BITS(bB[q][sel], e0), b1 = BITS(bB[q][sel], e1);
#pragma unroll
                for (int mf = 0; mf < 2; ++mf) {
                    mma_tf32(acc[mf][q],
                             BITS(aA[2 * mf][sel], e0), BITS(aA[2 * mf + 1][sel], e0),
                             BITS(aA[2 * mf][sel], e1), BITS(aA[2 * mf + 1][sel], e1),
                             b0, b1);
                }
            }
        }
    }
}

// ---- pre-pass: permute + tf32-round W1/W2 into Wp ----
__global__ void permute_w_kernel(const float* __restrict__ W1, const float* __restrict__ W2) {
    int r = blockIdx.x;              // 0..511
    int k = threadIdx.x;             // 0..255
    int n = r & 255;
    const float* W = (r < 256) ? W1 : W2;
    Wp[r >> 8][n][perm32(k)] = tfr(W[n * 256 + k]);
}

__global__ __launch_bounds__(THREADS, 1)
void fusion_block_kernel(
    const float* __restrict__ Qg_, const float* __restrict__ Kg_,
    const float* __restrict__ Vg_, const float* __restrict__ Mg_,
    const float* __restrict__ b1, const float* __restrict__ b2,
    const float* __restrict__ ln1w, const float* __restrict__ ln1b,
    const float* __restrict__ ln2w, const float* __restrict__ ln2b,
    float* __restrict__ Out)
{
    extern __shared__ float sm[];
    float* sX  = sm + OFF_X;    // Q -> x residual (E-permuted, fp32)
    float* sK  = sm + OFF_K;    // K (E-perm, rounded) -> H (E2-perm)
    float* sR3 = sm + OFF_R3;   // sVT [256 e][p-perm] -> W double buffer
    float* sS  = sm + OFF_S;    // scores/probs (p-permuted cols)
    const uint32_t sR3_u32 = (uint32_t)__cvta_generic_to_shared(sR3);

    const int tid  = threadIdx.x;
    const int warp = tid >> 5;
    const int lane = tid & 31;
    const int g    = lane >> 2;
    const int t    = lane & 3;

    const int bid = blockIdx.x;
    const int bt  = bid / Dn;
    const int d   = bid - bt * Dn;
    const int b   = bt / Tn;
    const int bd  = b * Dn + d;

    const float* Qg = Qg_ + (size_t)bt  * (Un * En);
    const float* Kg = Kg_ + (size_t)bd  * (Pn * En);
    const float* Vg = Vg_ + (size_t)bd  * (Pn * En);
    const float* Mg = Mg_ + (size_t)bid * (Un * Pn);
    float*       Og = Out + (size_t)bid * (Un * En);

    const float4 z4 = make_float4(0.f, 0.f, 0.f, 0.f);

    // ---- Load Q,K (E-permuted granule assembly; K RNA-rounded) ----
#pragma unroll
    for (int it = 0; it < 2; ++it) {
        int idx = tid + it * THREADS;   // 64 rows x 16 half-blocks
        int row = idx & 63;
        int hb  = idx >> 6;
        float4 q[4], k[4];
#pragma unroll
        for (int m = 0; m < 4; ++m) {
            if (row < Un) {
                q[m] = *reinterpret_cast<const float4*>(Qg + row * En + hb * 16 + m * 4);
                k[m] = *reinterpret_cast<const float4*>(Kg + row * En + hb * 16 + m * 4);
            } else { q[m] = z4; k[m] = z4; }
        }
        int dst = row * SA + (hb >> 1) * 32 + (hb & 1) * 4;
#pragma unroll
        for (int j0 = 0; j0 < 4; ++j0) {
            *reinterpret_cast<float4*>(sX + dst + j0 * 8) =
                make_float4(F4E(q[0], j0), F4E(q[1], j0), F4E(q[2], j0), F4E(q[3], j0));
            *reinterpret_cast<float4*>(sK + dst + j0 * 8) =
                make_float4(tfr(F4E(k[0], j0)), tfr(F4E(k[1], j0)),
                            tfr(F4E(k[2], j0)), tfr(F4E(k[3], j0)));
        }
    }
    // ---- Load V transposed (RNA-rounded): sVT[e][perm(p)] ----
#pragma unroll
    for (int it = 0; it < 8; ++it) {
        int idx = tid + it * THREADS;   // 64 p x 64 e-quads
        int p   = idx & 63;
        int eq  = idx >> 6;
        float4 v = (p < Un) ? *reinterpret_cast<const float4*>(Vg + p * En + eq * 4) : z4;
        int sp = perm32(p);
#pragma unroll
        for (int j = 0; j < 4; ++j)
            sR3[(eq * 4 + j) * SVT + sp] = tfr(F4E(v, j));
    }
    __syncthreads();

    // ---- S = Q K^T / 16 + mask  (warp tile m32 x n8; 16 warps cover 64x64) ----
    {
        const int mbS = (warp & 1) * 32;
        const int nbS = (warp >> 1) * 8;
        float acc[2][4] = {};
#pragma unroll
        for (int kb = 0; kb < 8; ++kb) {
            float4 aA[4][2];
#pragma unroll
            for (int r4 = 0; r4 < 4; ++r4) {
                int row = mbS + (r4 & 1) * 8 + (r4 >> 1) * 16 + g;
                const float* p = sX + row * SA + kb * 32 + 8 * t;
                aA[r4][0] = *reinterpret_cast<const float4*>(p);
                aA[r4][1] = *reinterpret_cast<const float4*>(p + 4);
            }
            const float* pk = sK + (nbS + g) * SA + kb * 32 + 8 * t;
            float4 b0v = *reinterpret_cast<const float4*>(pk);
            float4 b1v = *reinterpret_cast<const float4*>(pk + 4);
#pragma unroll
            for (int h = 0; h < 4; ++h) {
                const int sel = h >> 1, e0 = 2 * (h & 1), e1 = e0 + 1;
                const float4& bb = sel ? b1v : b0v;
#pragma unroll
                for (int mf = 0; mf < 2; ++mf)
                    mma_tf32(acc[mf],
                             BITS(aA[2 * mf][sel], e0), BITS(aA[2 * mf + 1][sel], e0),
                             BITS(aA[2 * mf][sel], e1), BITS(aA[2 * mf + 1][sel], e1),
                             BITS(bb, e0), BITS(bb, e1));
            }
        }
        const float inv_scale = 1.0f / 16.0f;  // sqrt(256)+1e-8 == 16.0f
#pragma unroll
        for (int mf = 0; mf < 2; ++mf)
#pragma unroll
            for (int r = 0; r < 4; ++r) {
                int u = mbS + mf * 16 + g + (r >= 2 ? 8 : 0);
                int p = nbS + 2 * t + (r & 1);
                float s = acc[mf][r] * inv_scale;
                if (u < Un && p < Pn) s += Mg[u * Pn + p];
                sS[u * SSs + perm32(p)] = s;
            }
    }
    __syncthreads();

    // ---- softmax over p (cols p-permuted); probs RNA-rounded; 4 rows/warp ----
    {
        const bool val1 = (inv32lo(lane) < Pn - 32);
#pragma unroll
        for (int r = 0; r < 4; ++r) {
            int row = warp * 4 + r;
            float v0 = sS[row * SSs + lane];
            float v1 = val1 ? sS[row * SSs + lane + 32] : -1e30f;
            float m  = wmax(fmaxf(v0, v1));
            float e0 = __expf(v0 - m);
            float e1 = val1 ? __expf(v1 - m) : 0.f;
            float inv = 1.f / wsum(e0 + e1);
            sS[row * SSs + lane]      = tfr(e0 * inv);
            sS[row * SSs + lane + 32] = tfr(e1 * inv);
        }
    }
    __syncthreads();

    const int mb = (warp & 1) * 32;
    const int nb = (warp >> 1) * 32;

    // ---- v_att = S @ V (warp tile m32 x n32); x = Q + v_att ----
    {
        float acc[2][4][4] = {};
#pragma unroll
        for (int kb = 0; kb < 2; ++kb) {
            float4 aA[4][2];
#pragma unroll
            for (int r4 = 0; r4 < 4; ++r4) {
                int row = mb + (r4 & 1) * 8 + (r4 >> 1) * 16 + g;
                const float* p = sS + row * SSs + kb * 32 + 8 * t;
                aA[r4][0] = *reinterpret_cast<const float4*>(p);
                aA[r4][1] = *reinterpret_cast<const float4*>(p + 4);
            }
            float4 bB[4][2];
#pragma unroll
            for (int q = 0; q < 4; ++q) {
                const float* p = sR3 + (nb + q * 8 + g) * SVT + kb * 32 + 8 * t;
                bB[q][0] = *reinterpret_cast<const float4*>(p);
                bB[q][1] = *reinterpret_cast<const float4*>(p + 4);
            }
#pragma unroll
            for (int h = 0; h < 4; ++h) {
                const int sel = h >> 1, e0 = 2 * (h & 1), e1 = e0 + 1;
#pragma unroll
                for (int q = 0; q < 4; ++q) {
                    uint32_t b0 = BITS(bB[q][sel], e0), b1 = BITS(bB[q][sel], e1);
#pragma unroll
                    for (int mf = 0; mf < 2; ++mf)
                        mma_tf32(acc[mf][q],
                                 BITS(aA[2 * mf][sel], e0), BITS(aA[2 * mf + 1][sel], e0),
                                 BITS(aA[2 * mf][sel], e1), BITS(aA[2 * mf + 1][sel], e1),
                                 b0, b1);
                }
            }
        }
#pragma unroll
        for (int mf = 0; mf < 2; ++mf)
#pragma unroll
            for (int q = 0; q < 4; ++q) {
                int row0 = mb + mf * 16 + g;
                int col  = nb + q * 8 + 2 * t;
                int sc0 = perm32(col), sc1 = perm32(col + 1);
                sX[row0 * SA + sc0]       += acc[mf][q][0];
                sX[row0 * SA + sc1]       += acc[mf][q][1];
                sX[(row0 + 8) * SA + sc0] += acc[mf][q][2];
                sX[(row0 + 8) * SA + sc1] += acc[mf][q][3];
            }
    }
    __syncthreads();

    // ---- LN1 (4 rows per warp; weights via inverse perm) ----
    {
#pragma unroll
        for (int r = 0; r < 4; ++r) {
            int row = warp * 4 + r;
            float xv[8];
            float s = 0.f;
#pragma unroll
            for (int kk = 0; kk < 8; ++kk) { xv[kk] = sX[row * SA + lane + kk * 32]; s += xv[kk]; }
            float mu = wsum(s) * (1.f / En);
            float vs = 0.f;
#pragma unroll
            for (int kk = 0; kk < 8; ++kk) { float t2 = xv[kk] - mu; vs += t2 * t2; }
            float rstd = rsqrtf(wsum(vs) * (1.f / En) + 1e-5f);
            int eb = inv32lo(lane);
#pragma unroll
            for (int kk = 0; kk < 8; ++kk) {
                int e = kk * 32 + eb;
                sX[row * SA + lane + kk * 32] = (xv[kk] - mu) * rstd * ln1w[e] + ln1b[e];
            }
        }
    }
    // (first barrier inside ffn_mma orders LN1 writes, retires sVT region)

    // ---- FFN1: H = relu(x @ W1^T + b1) -> sK (E2-permuted) ----
    {
        float acc[2][4][4] = {};
        ffn_mma(0, sX, sR3, sR3_u32, acc, tid, g, t, mb, nb);
#pragma unroll
        for (int mf = 0; mf < 2; ++mf)
#pragma unroll
            for (int q = 0; q < 4; ++q) {
                int row0 = mb + mf * 16 + g;
                int col  = nb + q * 8 + 2 * t;
                float bb0 = __ldg(b1 + col), bb1 = __ldg(b1 + col + 1);
                int sc0 = perm32(col), sc1 = perm32(col + 1);
                sK[row0 * SA + sc0]       = fmaxf(acc[mf][q][0] + bb0, 0.f);
                sK[row0 * SA + sc1]       = fmaxf(acc[mf][q][1] + bb1, 0.f);
                sK[(row0 + 8) * SA + sc0] = fmaxf(acc[mf][q][2] + bb0, 0.f);
                sK[(row0 + 8) * SA + sc1] = fmaxf(acc[mf][q][3] + bb1, 0.f);
            }
    }

    // ---- FFN2: y = H @ W2^T + b2 + x (into sX, fp32) ----
    {
        float acc[2][4][4] = {};
        ffn_mma(1, sK, sR3, sR3_u32, acc, tid, g, t, mb, nb);
#pragma unroll
        for (int mf = 0; mf < 2; ++mf)
#pragma unroll
            for (int q = 0; q < 4; ++q) {
                int row0 = mb + mf * 16 + g;
                int col  = nb + q * 8 + 2 * t;
                float bb0 = __ldg(b2 + col), bb1 = __ldg(b2 + col + 1);
                int sc0 = perm32(col), sc1 = perm32(col + 1);
                sX[row0 * SA + sc0]       += acc[mf][q][0] + bb0;
                sX[row0 * SA + sc1]       += acc[mf][q][1] + bb1;
                sX[(row0 + 8) * SA + sc0] += acc[mf][q][2] + bb0;
                sX[(row0 + 8) * SA + sc1] += acc[mf][q][3] + bb1;
            }
    }
    __syncthreads();

    // ---- LN2 + store (4 rows/warp; de-permute; line-coalesced) ----
    {
#pragma unroll
        for (int r = 0; r < 4; ++r) {
            int row = warp * 4 + r;
            if (row >= Un) continue;    // predicated; pad rows not stored
            float xv[8];
            float s = 0.f;
#pragma unroll
            for (int kk = 0; kk < 8; ++kk) { xv[kk] = sX[row * SA + lane + kk * 32]; s += xv[kk]; }
            float mu = wsum(s) * (1.f / En);
            float vs = 0.f;
#pragma unroll
            for (int kk = 0; kk < 8; ++kk) { float t2 = xv[kk] - mu; vs += t2 * t2; }
            float rstd = rsqrtf(wsum(vs) * (1.f / En) + 1e-5f);
            int eb = inv32lo(lane);
#pragma unroll
            for (int kk = 0; kk < 8; ++kk) {
                int e = kk * 32 + eb;
                Og[row * En + e] = (xv[kk] - mu) * rstd * ln2w[e] + ln2b[e];
            }
        }
    }
}

extern "C" void kernel_launch(void* const* d_in, const int* in_sizes, int n_in,
                              void* d_out, int out_size) {
    (void)in_sizes; (void)n_in; (void)out_size;
    permute_w_kernel<<<512, 256>>>((const float*)d_in[4], (const float*)d_in[6]);
    cudaFuncSetAttribute(fusion_block_kernel,
                         cudaFuncAttributeMaxDynamicSharedMemorySize, SMEM_BYTES);
    fusion_block_kernel<<<Bn * Tn * Dn, THREADS, SMEM_BYTES>>>(
        (const float*)d_in[0],  // Q
        (const float*)d_in[1],  // K
        (const float*)d_in[2],  // V
        (const float*)d_in[3],  // attention_mask
        (const float*)d_in[5],  // b1
        (const float*)d_in[7],  // b2
        (const float*)d_in[8],  // ln1_w
        (const float*)d_in[9],  // ln1_b
        (const float*)d_in[10], // ln2_w
        (const float*)d_in[11], // ln2_b
        (float*)d_out);
}